// round 1
// baseline (speedup 1.0000x reference)
#include <cuda_runtime.h>
#include <cuda_bf16.h>

// OctonionLinear == dense GEMM with a blocked weight layout:
//   Y[b, n] = sum_kk X[b, kk] * W[(n>>3)*32768 + (kk>>3)*64 + (kk&7)*8 + (n&7)] + bias[n]
// M=512, N=4096, K=4096.

#define M_DIM 512
#define N_DIM 4096
#define K_DIM 4096

#define BM 128
#define BN 128
#define BK 8
#define TM 8
#define TN 8

__global__ __launch_bounds__(256, 2)
void octlinear_sgemm(const float* __restrict__ X,
                     const float* __restrict__ W,
                     const float* __restrict__ Bias,
                     float* __restrict__ Y)
{
    __shared__ float As[BK][BM];   // k-major A tile (transposed on load)
    __shared__ float Bs[BK][BN];

    const int t  = threadIdx.x;
    const int tx = t & 15;         // 0..15 -> N microtile
    const int ty = t >> 4;         // 0..15 -> M microtile
    const int bm = blockIdx.y * BM;
    const int bn = blockIdx.x * BN;

    // ---- A-load mapping: 128 rows x 8 cols, one float4 per thread ----
    const int ar  = t >> 1;        // 0..127  (row within tile)
    const int ac4 = (t & 1) * 4;   // 0 or 4  (col within BK)
    const float* aptr = X + (size_t)(bm + ar) * K_DIM + ac4;

    // ---- B-load mapping: 8 rows (p) x 128 cols (n), one float4 per thread ----
    // kk = kt*8 + p  (so j = kt, p = kk&7); n = bn + c, i = n>>3, k = n&7
    // W offset = i*32768 + j*64 + p*8 + k
    const int bp   = t >> 5;        // 0..7   (p)
    const int bc4  = (t & 31) * 4;  // 0..124 (col, float4 stays inside one octet)
    const int boct = bc4 >> 3;      // i offset within tile
    const int bkin = bc4 & 7;       // k within octet
    const int i0   = bn >> 3;
    const float* bptr = W + (size_t)(i0 + boct) * 32768 + bp * 8 + bkin;

    float acc[TM][TN];
    #pragma unroll
    for (int i = 0; i < TM; i++)
        #pragma unroll
        for (int j = 0; j < TN; j++) acc[i][j] = 0.0f;

    for (int kt = 0; kt < K_DIM / BK; kt++) {
        // global loads
        float4 av = *(const float4*)(aptr + (size_t)kt * BK);
        float4 bv = *(const float4*)(bptr + (size_t)kt * 64);  // j advances by 1 per kt

        As[ac4 + 0][ar] = av.x;
        As[ac4 + 1][ar] = av.y;
        As[ac4 + 2][ar] = av.z;
        As[ac4 + 3][ar] = av.w;
        *(float4*)&Bs[bp][bc4] = bv;
        __syncthreads();

        #pragma unroll
        for (int k = 0; k < BK; k++) {
            float a[TM], b[TN];
            float4 a0 = *(const float4*)&As[k][ty * TM];
            float4 a1 = *(const float4*)&As[k][ty * TM + 4];
            float4 b0 = *(const float4*)&Bs[k][tx * TN];
            float4 b1 = *(const float4*)&Bs[k][tx * TN + 4];
            a[0] = a0.x; a[1] = a0.y; a[2] = a0.z; a[3] = a0.w;
            a[4] = a1.x; a[5] = a1.y; a[6] = a1.z; a[7] = a1.w;
            b[0] = b0.x; b[1] = b0.y; b[2] = b0.z; b[3] = b0.w;
            b[4] = b1.x; b[5] = b1.y; b[6] = b1.z; b[7] = b1.w;
            #pragma unroll
            for (int i = 0; i < TM; i++)
                #pragma unroll
                for (int j = 0; j < TN; j++)
                    acc[i][j] = fmaf(a[i], b[j], acc[i][j]);
        }
        __syncthreads();
    }

    // ---- epilogue: add bias (bias[n] flattened over (i,k)) and store ----
    const int mrow = bm + ty * TM;
    const int ncol = bn + tx * TN;
    float bs[TN];
    #pragma unroll
    for (int j = 0; j < TN; j++) bs[j] = Bias[ncol + j];

    #pragma unroll
    for (int i = 0; i < TM; i++) {
        float4 o0, o1;
        o0.x = acc[i][0] + bs[0];
        o0.y = acc[i][1] + bs[1];
        o0.z = acc[i][2] + bs[2];
        o0.w = acc[i][3] + bs[3];
        o1.x = acc[i][4] + bs[4];
        o1.y = acc[i][5] + bs[5];
        o1.z = acc[i][6] + bs[6];
        o1.w = acc[i][7] + bs[7];
        float* yrow = Y + (size_t)(mrow + i) * N_DIM + ncol;
        *(float4*)(yrow)     = o0;
        *(float4*)(yrow + 4) = o1;
    }
}

extern "C" void kernel_launch(void* const* d_in, const int* in_sizes, int n_in,
                              void* d_out, int out_size)
{
    const float* x    = (const float*)d_in[0];  // [512, 4096]
    const float* w    = (const float*)d_in[1];  // [512, 512, 8, 8]
    const float* bias = (const float*)d_in[2];  // [512, 8]
    float* y          = (float*)d_out;          // [512, 4096]

    dim3 grid(N_DIM / BN, M_DIM / BM);  // (32, 4) = 128 CTAs
    octlinear_sgemm<<<grid, 256>>>(x, w, bias, y);
}

// round 4
// speedup vs baseline: 5.1044x; 5.1044x over previous
#include <cuda_runtime.h>
#include <cstdint>

// OctonionLinear as dense tf32 mma.sync GEMM (portable sm_103 target — no tcgen05):
//   Y[b, n] = sum_kk X[b, kk] * Bop(n, kk) + bias[n]
//   Bop(n=8i+c, kk) = W[i*32768 + kk*8 + c]
// M=512, N=4096, K=4096.

#define M_DIM 512
#define N_DIM 4096
#define K_DIM 4096
#define BM 128
#define BN 128
#define BK 32
#define NK (K_DIM / BK)         // 128
#define STAGES 3
#define THREADS 256

#define A_STRIDE 36                       // padded floats per A row (conflict-free)
#define A_STAGE_FLT (BM * A_STRIDE)       // 4608
#define B_STAGE_FLT ((BN / 8) * BK * 8)   // 4096  ([16 oct][32 k][8 c])
#define SMEM_BYTES ((STAGES * (A_STAGE_FLT + B_STAGE_FLT)) * 4)  // 104448

__device__ __forceinline__ uint32_t smem_u32(const void* p) {
    uint32_t a;
    asm("{ .reg .u64 t; cvta.to.shared.u64 t, %1; cvt.u32.u64 %0, t; }" : "=r"(a) : "l"(p));
    return a;
}
__device__ __forceinline__ uint32_t f2tf(float f) {
    uint32_t r;
    asm("cvt.rna.tf32.f32 %0, %1;" : "=r"(r) : "f"(f));
    return r;
}
__device__ __forceinline__ void cp16(uint32_t dst, const void* src) {
    asm volatile("cp.async.cg.shared.global [%0], [%1], 16;" :: "r"(dst), "l"(src));
}
#define CP_COMMIT() asm volatile("cp.async.commit_group;" ::: "memory")
#define CP_WAIT(n)  asm volatile("cp.async.wait_group %0;" :: "n"(n) : "memory")

__device__ __forceinline__ void mma8(float* c, const uint32_t* a, const uint32_t* b) {
    asm volatile(
        "mma.sync.aligned.m16n8k8.row.col.f32.tf32.tf32.f32 "
        "{%0,%1,%2,%3}, {%4,%5,%6,%7}, {%8,%9}, {%0,%1,%2,%3};"
        : "+f"(c[0]), "+f"(c[1]), "+f"(c[2]), "+f"(c[3])
        : "r"(a[0]), "r"(a[1]), "r"(a[2]), "r"(a[3]), "r"(b[0]), "r"(b[1]));
}

__global__ __launch_bounds__(THREADS, 1)
void oct_mma_tf32(const float* __restrict__ X,
                  const float* __restrict__ W,
                  const float* __restrict__ Bias,
                  float* __restrict__ Y)
{
    extern __shared__ float smem[];
    float* As = smem;                            // [STAGES][128][36]
    float* Bs = smem + STAGES * A_STAGE_FLT;     // [STAGES][16][32][8]
    const uint32_t sA = smem_u32(As);
    const uint32_t sB = smem_u32(Bs);

    const int t = threadIdx.x;
    const int w = t >> 5;
    const int l = t & 31;
    const int bm = blockIdx.y * BM;
    const int bn = blockIdx.x * BN;
    const int wm = (w & 3) * 32;        // warp M base within tile
    const int wn = (w >> 2) * 64;       // warp N base within tile

    const int lr = l >> 2;              // 0..7
    const int lc = l & 3;               // 0..3

    // ---- cp.async mappings (per thread: 4 A chunks + 4 B chunks of 16 B) ----
    // A chunk id = t + r*256: row = id>>3 (0..127), c16 = id&7
    // B chunk id = t + r*256: oct = id>>6 (0..15), inner = id&63
    const int i0 = bn >> 3;

    auto issue_stage = [&](int kt, int s) {
        const uint32_t aBase = sA + (uint32_t)s * (A_STAGE_FLT * 4);
        const uint32_t bBase = sB + (uint32_t)s * (B_STAGE_FLT * 4);
        #pragma unroll
        for (int r = 0; r < 4; r++) {
            const int id = t + r * 256;
            const int row = id >> 3, c16 = id & 7;
            cp16(aBase + (uint32_t)row * (A_STRIDE * 4) + (uint32_t)c16 * 16,
                 X + (size_t)(bm + row) * K_DIM + (size_t)kt * BK + c16 * 4);
        }
        #pragma unroll
        for (int r = 0; r < 4; r++) {
            const int id = t + r * 256;
            const int oct = id >> 6, inner = id & 63;
            cp16(bBase + (uint32_t)oct * 1024 + (uint32_t)inner * 16,
                 W + (size_t)(i0 + oct) * 32768 + (size_t)kt * 256 + inner * 4);
        }
    };

    // ---- prologue: prefetch STAGES-1 stages ----
    #pragma unroll
    for (int s = 0; s < STAGES - 1; s++) {
        issue_stage(s, s);
        CP_COMMIT();
    }

    float acc[2][8][4];
    #pragma unroll
    for (int mi = 0; mi < 2; mi++)
        #pragma unroll
        for (int j = 0; j < 8; j++)
            #pragma unroll
            for (int q = 0; q < 4; q++) acc[mi][j][q] = 0.0f;

    for (int kt = 0; kt < NK; kt++) {
        const int s = kt % STAGES;
        CP_WAIT(STAGES - 2);
        __syncthreads();

        // prefetch stage kt+STAGES-1 into the slot freed last iteration
        {
            const int pf = kt + STAGES - 1;
            if (pf < NK) issue_stage(pf, pf % STAGES);
            CP_COMMIT();
        }

        const float* a = As + s * A_STAGE_FLT;
        const float* b = Bs + s * B_STAGE_FLT;

        #pragma unroll
        for (int ks = 0; ks < 4; ks++) {
            const int k0 = ks * 8;
            uint32_t af[2][4], bf[8][2];
            #pragma unroll
            for (int mi = 0; mi < 2; mi++) {
                const int row = wm + mi * 16 + lr;
                af[mi][0] = f2tf(a[row * A_STRIDE + k0 + lc]);
                af[mi][1] = f2tf(a[(row + 8) * A_STRIDE + k0 + lc]);
                af[mi][2] = f2tf(a[row * A_STRIDE + k0 + 4 + lc]);
                af[mi][3] = f2tf(a[(row + 8) * A_STRIDE + k0 + 4 + lc]);
            }
            #pragma unroll
            for (int j = 0; j < 8; j++) {
                const int oct = (wn >> 3) + j;
                bf[j][0] = f2tf(b[oct * 256 + (k0 + lc) * 8 + lr]);
                bf[j][1] = f2tf(b[oct * 256 + (k0 + 4 + lc) * 8 + lr]);
            }
            #pragma unroll
            for (int mi = 0; mi < 2; mi++)
                #pragma unroll
                for (int j = 0; j < 8; j++)
                    mma8(acc[mi][j], af[mi], bf[j]);
        }
    }

    // ---- epilogue: bias add + store (c-frag: rows lr, lr+8; cols 2*lc, 2*lc+1) ----
    const int r0 = bm + wm + lr;
    #pragma unroll
    for (int mi = 0; mi < 2; mi++) {
        #pragma unroll
        for (int j = 0; j < 8; j++) {
            const int n0 = bn + wn + j * 8 + lc * 2;
            const float b0v = Bias[n0];
            const float b1v = Bias[n0 + 1];
            float2 v0 = make_float2(acc[mi][j][0] + b0v, acc[mi][j][1] + b1v);
            float2 v1 = make_float2(acc[mi][j][2] + b0v, acc[mi][j][3] + b1v);
            *(float2*)(Y + (size_t)(r0 + mi * 16) * N_DIM + n0) = v0;
            *(float2*)(Y + (size_t)(r0 + mi * 16 + 8) * N_DIM + n0) = v1;
        }
    }
}

extern "C" void kernel_launch(void* const* d_in, const int* in_sizes, int n_in,
                              void* d_out, int out_size)
{
    const float* x    = (const float*)d_in[0];  // [512, 4096]
    const float* wt   = (const float*)d_in[1];  // [512, 512, 8, 8]
    const float* bias = (const float*)d_in[2];  // [512, 8]
    float* y          = (float*)d_out;          // [512, 4096]

    cudaFuncSetAttribute(oct_mma_tf32, cudaFuncAttributeMaxDynamicSharedMemorySize, SMEM_BYTES);
    dim3 grid(N_DIM / BN, M_DIM / BM);  // (32, 4) = 128 CTAs
    oct_mma_tf32<<<grid, THREADS, SMEM_BYTES>>>(x, wt, bias, y);
}